// round 12
// baseline (speedup 1.0000x reference)
#include <cuda_runtime.h>
#include <cstdint>

#define E    512
#define HD   256
#define MTXT 2048
#define MVID 8192
#define NSPLIT 4
#define KSPL  2048

#define BM 128
#define BN 128
#define BK 32
#define SSTR 36    // smem row stride in floats (ldmatrix conflict-free)
#define STAGEF ((BM + BN) * SSTR)        // floats per double-buffer stage
#define SMEM_BYTES (2 * STAGEF * 4)      // 73728 B

// ---------------- device scratch ----------------
__device__ float g_Q[(long long)MTXT * E];
__device__ float g_K[(long long)MVID * E];
__device__ float g_Vt[2ll * HD * MVID];
__device__ float g_Wt[2ll * MTXT * MVID];
__device__ float g_part[(long long)NSPLIT * MTXT * E];

__device__ __forceinline__ float rntf32(float x) {
    uint32_t u; asm("cvt.rna.tf32.f32 %0, %1;" : "=r"(u) : "f"(x));
    return __uint_as_float(u);
}
__device__ __forceinline__ uint32_t smem_u32(const void* p) {
    uint32_t a;
    asm("{ .reg .u64 t; cvta.to.shared.u64 t, %1; cvt.u32.u64 %0, t; }" : "=r"(a) : "l"(p));
    return a;
}
__device__ __forceinline__ void mma_tf32(float* c, const uint32_t* a, const uint32_t* b) {
    asm volatile(
        "mma.sync.aligned.m16n8k8.row.col.f32.tf32.tf32.f32 "
        "{%0,%1,%2,%3}, {%4,%5,%6,%7}, {%8,%9}, {%0,%1,%2,%3};"
        : "+f"(c[0]), "+f"(c[1]), "+f"(c[2]), "+f"(c[3])
        : "r"(a[0]), "r"(a[1]), "r"(a[2]), "r"(a[3]), "r"(b[0]), "r"(b[1]));
}
__device__ __forceinline__ void ldsm_x4(uint32_t* r, uint32_t addr) {
    asm volatile("ldmatrix.sync.aligned.m8n8.x4.shared.b16 {%0,%1,%2,%3}, [%4];"
        : "=r"(r[0]), "=r"(r[1]), "=r"(r[2]), "=r"(r[3]) : "r"(addr));
}

// ---------------------------------------------------------------------------
// tf32 mma.sync GEMM: D[m,n] = sum_k A[m,k] * B[n,k]  (both K-major)
// Schedule per stage: sync -> STS(s+1) -> LDG(s+2) -> compute(s).
// ROUND: loader applies rna->tf32 + nparts-sum; false = pre-rounded inputs.
// epi: 0 = bias+store (final)            1 = Vt transpose store (rounded)
//      3 = attn scatter (torch reshape)  4 = bias+store rounded (Q/K)
//      5 = fused softmax-over-frames -> Wt[h][bt][av] (rounded, /16, /128)
// ---------------------------------------------------------------------------
template<bool ROUND>
__global__ __launch_bounds__(256, 2) void gemm_mma(
    const float* __restrict__ A, int lda, long long aH, long long aS,
    const float* __restrict__ B, int ldb, long long bH, long long bS,
    const float* __restrict__ bias, float* __restrict__ D,
    int K, int nsplit, int nparts, long long pStride,
    int epi, int ldd, long long dH, float scale)
{
    extern __shared__ float smem[];

    const int tid  = threadIdx.x;
    const int warp = tid >> 5;
    const int lane = tid & 31;
    const int gid  = lane >> 2;
    const int tig  = lane & 3;
    const int wm   = warp & 1;
    const int wn   = warp >> 1;

    const int zh = blockIdx.z / nsplit;
    const int zs = blockIdx.z % nsplit;
    const int m0 = blockIdx.y * BM;
    const int n0 = blockIdx.x * BN;
    const float* Ab = A + zh * aH + zs * aS;
    const float* Bb = B + zh * bH + zs * bS;

    float acc[4][4][4];
#pragma unroll
    for (int i = 0; i < 4; i++)
#pragma unroll
        for (int j = 0; j < 4; j++)
#pragma unroll
            for (int c = 0; c < 4; c++) acc[i][j][c] = 0.0f;

    // ldmatrix per-lane source rows/cols (buffer 0; +stageB for buffer 1)
    const int lrA  = ((lane >> 3) & 1) * 8 + (lane & 7);
    const int lcA  = (lane >> 4) * 4;
    const int lrB4 = (lane & 7) + ((lane >> 4) & 1) * 8;
    const int lcB4 = ((lane >> 3) & 1) * 4;
    const uint32_t baseU  = smem_u32(smem);
    const uint32_t stageB = (uint32_t)(STAGEF * 4);
    uint32_t aAddr[4], bAddr[2];
#pragma unroll
    for (int mt = 0; mt < 4; mt++)
        aAddr[mt] = baseU + (uint32_t)(((wm * 64 + mt * 16 + lrA) * SSTR + lcA) * 4);
#pragma unroll
    for (int p = 0; p < 2; p++)
        bAddr[p] = baseU + (uint32_t)((BM * SSTR + (wn * 32 + p * 16 + lrB4) * SSTR + lcB4) * 4);

    const int lm = tid >> 3;          // 0..31 base load row
    const int lk = (tid & 7) << 2;    // 0..28 load col
    const int S = K / BK;

    float4 ra[4], rb[4];

    auto ldg_stage = [&](int s) {
        const int k0 = s * BK;
#pragma unroll
        for (int i = 0; i < 4; i++) {
            const int r = lm + i * 32;
            const float* ap = Ab + (long long)(m0 + r) * lda + k0 + lk;
            float4 v = *(const float4*)ap;
            if (ROUND) {
                for (int p = 1; p < nparts; p++) {
                    float4 w = *(const float4*)(ap + (long long)p * pStride);
                    v.x += w.x; v.y += w.y; v.z += w.z; v.w += w.w;
                }
                v = make_float4(rntf32(v.x), rntf32(v.y), rntf32(v.z), rntf32(v.w));
            }
            ra[i] = v;
            float4 u = *(const float4*)(Bb + (long long)(n0 + r) * ldb + k0 + lk);
            if (ROUND)
                u = make_float4(rntf32(u.x), rntf32(u.y), rntf32(u.z), rntf32(u.w));
            rb[i] = u;
        }
    };
    auto sts_stage = [&](int bu) {
        float* As = smem + bu * STAGEF;
        float* Bs = As + BM * SSTR;
#pragma unroll
        for (int i = 0; i < 4; i++) {
            const int r = lm + i * 32;
            *(float4*)&As[r * SSTR + lk] = ra[i];
            *(float4*)&Bs[r * SSTR + lk] = rb[i];
        }
    };
    auto compute = [&](int bu) {
        const uint32_t off = bu * stageB;
#pragma unroll
        for (int ks = 0; ks < 4; ks++) {
            const uint32_t kb = (uint32_t)(ks * 8 * 4) + off;
            uint32_t af[4][4], bq[2][4];
#pragma unroll
            for (int mt = 0; mt < 4; mt++) ldsm_x4(af[mt], aAddr[mt] + kb);
#pragma unroll
            for (int p = 0; p < 2; p++)  ldsm_x4(bq[p], bAddr[p] + kb);
#pragma unroll
            for (int mt = 0; mt < 4; mt++)
#pragma unroll
                for (int nt = 0; nt < 4; nt++)
                    mma_tf32(acc[mt][nt], af[mt], &bq[nt >> 1][(nt & 1) * 2]);
        }
    };

    // prologue: stage 0 in smem, stage 1 in regs
    ldg_stage(0);
    sts_stage(0);
    if (S > 1) ldg_stage(1);
    for (int s = 0; s < S; s++) {
        __syncthreads();                        // buf (s+1)&1 now free; buf s&1 ready
        if (s + 1 < S) sts_stage((s + 1) & 1);  // regs -> smem, one stage ahead
        if (s + 2 < S) ldg_stage(s + 2);        // gmem -> regs, two stages ahead
        compute(s & 1);
    }

    // ---------------- epilogues ----------------
    if (epi == 5) {
        // Fused softmax over the 64 frame-rows of this thread's wm-half
        // (one complete video), transposed store to Wt[h][bt][av].
#pragma unroll
        for (int nt = 0; nt < 4; nt++) {
#pragma unroll
            for (int p = 0; p < 2; p++) {
                float m = -1e30f;
#pragma unroll
                for (int mt = 0; mt < 4; mt++)
                    m = fmaxf(m, fmaxf(acc[mt][nt][p], acc[mt][nt][p + 2]));
                m = fmaxf(m, __shfl_xor_sync(0xffffffffu, m, 4));
                m = fmaxf(m, __shfl_xor_sync(0xffffffffu, m, 8));
                m = fmaxf(m, __shfl_xor_sync(0xffffffffu, m, 16));
                float sum = 0.0f;
#pragma unroll
                for (int mt = 0; mt < 4; mt++) {
                    float e0 = __expf((acc[mt][nt][p]     - m) * 0.0625f);
                    float e1 = __expf((acc[mt][nt][p + 2] - m) * 0.0625f);
                    acc[mt][nt][p]     = e0;
                    acc[mt][nt][p + 2] = e1;
                    sum += e0 + e1;
                }
                sum += __shfl_xor_sync(0xffffffffu, sum, 4);
                sum += __shfl_xor_sync(0xffffffffu, sum, 8);
                sum += __shfl_xor_sync(0xffffffffu, sum, 16);
                const float inv = 1.0f / (128.0f * sum);
                const int bt = n0 + wn * 32 + nt * 8 + 2 * tig + p;
                const int rb2 = m0 + wm * 64 + gid;
                float* Wc = D + (long long)zh * dH + (long long)bt * MVID;
#pragma unroll
                for (int mt = 0; mt < 4; mt++) {
                    Wc[rb2 + mt * 16    ] = rntf32(acc[mt][nt][p]     * inv);
                    Wc[rb2 + mt * 16 + 8] = rntf32(acc[mt][nt][p + 2] * inv);
                }
            }
        }
        return;
    }

#pragma unroll
    for (int mt = 0; mt < 4; mt++) {
#pragma unroll
        for (int nt = 0; nt < 4; nt++) {
            const int r0 = m0 + wm * 64 + mt * 16 + gid;
            const int cN = n0 + wn * 32 + nt * 8 + 2 * tig;
#pragma unroll
            for (int half = 0; half < 2; half++) {
                const int r = r0 + half * 8;
                float x = acc[mt][nt][half * 2 + 0];
                float y = acc[mt][nt][half * 2 + 1];
                if (epi == 0) {
                    float2 o = make_float2(x * scale + bias[cN],
                                           y * scale + bias[cN + 1]);
                    *(float2*)&D[dH * zh + (long long)r * ldd + cN] = o;
                } else if (epi == 4) {
                    float2 o = make_float2(rntf32(x * scale + bias[cN]),
                                           rntf32(y * scale + bias[cN + 1]));
                    *(float2*)&D[dH * zh + (long long)r * ldd + cN] = o;
                } else if (epi == 1) {
                    // Vt: n = h*256 + d  ->  D[(h*HD+d)*MVID + m], rounded
                    D[(long long)(cN    ) * MVID + r] = rntf32(x);
                    D[(long long)(cN + 1) * MVID + r] = rntf32(y);
                } else {
                    // attn scatter: m = b*32+t, n = d (torch reshape layout)
                    long long addr = (long long)zs * pStride
                                   + (long long)(r >> 5) * 16384
                                   + (long long)zh * 8192
                                   + (r & 31) * 256 + cN;
                    *(float2*)&D[addr] = make_float2(x, y);
                }
            }
        }
    }
}

// ---------------------------------------------------------------------------
extern "C" void kernel_launch(void* const* d_in, const int* in_sizes, int n_in,
                              void* d_out, int out_size)
{
    const float* text  = (const float*)d_in[0];
    const float* video = (const float*)d_in[1];
    const float* Wq = (const float*)d_in[2];
    const float* bq = (const float*)d_in[3];
    const float* Wk = (const float*)d_in[4];
    const float* bk = (const float*)d_in[5];
    const float* Wv = (const float*)d_in[6];
    const float* bv = (const float*)d_in[7];
    const float* Wo = (const float*)d_in[8];
    const float* bo = (const float*)d_in[9];
    float* out = (float*)d_out;

    float *Qp, *Kp, *Vtp, *Wtp, *Pp;
    cudaGetSymbolAddress((void**)&Qp,  g_Q);
    cudaGetSymbolAddress((void**)&Kp,  g_K);
    cudaGetSymbolAddress((void**)&Vtp, g_Vt);
    cudaGetSymbolAddress((void**)&Wtp, g_Wt);
    cudaGetSymbolAddress((void**)&Pp,  g_part);

    cudaFuncSetAttribute(gemm_mma<true>,
                         cudaFuncAttributeMaxDynamicSharedMemorySize, SMEM_BYTES);
    cudaFuncSetAttribute(gemm_mma<false>,
                         cudaFuncAttributeMaxDynamicSharedMemorySize, SMEM_BYTES);

    dim3 t(256);

    // Q/K projections, tf32-rounded outputs (epi4); V with transpose+round (epi1)
    gemm_mma<true><<<dim3(4, 16, 1), t, SMEM_BYTES>>>(text, 512, 0, 0,  Wq, 512, 0, 0,
        bq, Qp, 512, 1, 1, 0, 4, 512, 0, 1.0f);
    gemm_mma<true><<<dim3(4, 64, 1), t, SMEM_BYTES>>>(video, 512, 0, 0, Wk, 512, 0, 0,
        bk, Kp, 512, 1, 1, 0, 4, 512, 0, 1.0f);
    gemm_mma<true><<<dim3(4, 64, 1), t, SMEM_BYTES>>>(video, 512, 0, 0, Wv, 512, 0, 0,
        bv, Vtp, 512, 1, 1, 0, 1, 0, 0, 1.0f);

    // Logits + fused softmax (epi5): writes Wt[h][bt][av] directly
    gemm_mma<false><<<dim3(16, 64, 2), t, SMEM_BYTES>>>(Kp, 512, 256, 0, Qp, 512, 256, 0,
        nullptr, Wtp, 256, 1, 1, 0, 5, 0, (long long)MTXT * MVID, 1.0f);

    // Attention: D[bt, d] = sum_av Wt[bt,av] * Vt[d,av], split-K x4 (epi3)
    gemm_mma<false><<<dim3(2, 16, 2 * NSPLIT), t, SMEM_BYTES>>>(Wtp, MVID,
        (long long)MTXT * MVID, KSPL,
        Vtp, MVID, (long long)HD * MVID, KSPL,
        nullptr, Pp, KSPL, NSPLIT, 1, (long long)MTXT * E, 3, 0, 0, 1.0f);

    // Output projection, summing the 4 split-K partials during A-load (epi0)
    gemm_mma<true><<<dim3(4, 16, 1), t, SMEM_BYTES>>>(Pp, 512, 0, 0, Wo, 512, 0, 0,
        bo, out, 512, 1, NSPLIT, (long long)MTXT * E, 0, 512, 0, 1.0f);
}

// round 13
// speedup vs baseline: 1.0676x; 1.0676x over previous
#include <cuda_runtime.h>
#include <cuda_fp16.h>
#include <cstdint>

#define E    512
#define HD   256
#define MTXT 2048
#define MVID 8192
#define NSPLIT 4
#define KSPL  2048

#define BM 128
#define BN 128
#define BK 32        // k-elements per stage (2 x k16 mma steps)
#define HSTR 40      // smem row stride in halves (ldmatrix + STS conflict-free)
#define STAGEF ((BM + BN) * HSTR)   // halves per stage = 10240 (20480 B)

// ---------------- device scratch ----------------
__device__ __half g_Qh[(long long)MTXT * E];
__device__ __half g_Kh[(long long)MVID * E];
__device__ __half g_Vth[2ll * HD * MVID];
__device__ __half g_Wth[2ll * MTXT * MVID];
__device__ float  g_part[(long long)NSPLIT * MTXT * E];

__device__ __forceinline__ uint32_t smem_u32(const void* p) {
    uint32_t a;
    asm("{ .reg .u64 t; cvta.to.shared.u64 t, %1; cvt.u32.u64 %0, t; }" : "=r"(a) : "l"(p));
    return a;
}
__device__ __forceinline__ uint32_t packh2(float a, float b) {
    __half2 h = __floats2half2_rn(a, b);
    return *reinterpret_cast<uint32_t*>(&h);
}
__device__ __forceinline__ void mma_f16(float* c, const uint32_t* a,
                                        uint32_t b0, uint32_t b1) {
    asm volatile(
        "mma.sync.aligned.m16n8k16.row.col.f32.f16.f16.f32 "
        "{%0,%1,%2,%3}, {%4,%5,%6,%7}, {%8,%9}, {%0,%1,%2,%3};"
        : "+f"(c[0]), "+f"(c[1]), "+f"(c[2]), "+f"(c[3])
        : "r"(a[0]), "r"(a[1]), "r"(a[2]), "r"(a[3]), "r"(b0), "r"(b1));
}
__device__ __forceinline__ void ldsm_x4(uint32_t* r, uint32_t addr) {
    asm volatile("ldmatrix.sync.aligned.m8n8.x4.shared.b16 {%0,%1,%2,%3}, [%4];"
        : "=r"(r[0]), "=r"(r[1]), "=r"(r[2]), "=r"(r[3]) : "r"(addr));
}

// ---------------------------------------------------------------------------
// fp16 mma.sync GEMM (fp32 accum): D[m,n] = sum_k A[m,k]*B[n,k]  (K-major)
// ROUND=true : A,B are fp32 (optionally nparts-summed), converted rn->fp16.
// ROUND=false: A,B are pre-converted __half.
// epi: 0 = bias+store fp32 (final)      1 = Vt transpose store (half)
//      3 = attn scatter fp32 (reshape)  4 = bias+store half (Q/K)
//      5 = fused softmax-over-frames -> Wt[h][bt][av] (half, /16, /128)
// ---------------------------------------------------------------------------
template<bool ROUND>
__global__ __launch_bounds__(256, 2) void gemm_mma(
    const void* __restrict__ Av, int lda, long long aH, long long aS,
    const void* __restrict__ Bv, int ldb, long long bH, long long bS,
    const float* __restrict__ bias, void* __restrict__ Dv,
    int K, int nsplit, int nparts, long long pStride,
    int epi, int ldd, long long dH, float scale)
{
    __shared__ __align__(16) __half smem[2 * STAGEF];

    const int tid  = threadIdx.x;
    const int warp = tid >> 5;
    const int lane = tid & 31;
    const int gid  = lane >> 2;
    const int tig  = lane & 3;
    const int wm   = warp & 1;
    const int wn   = warp >> 1;

    const int zh = blockIdx.z / nsplit;
    const int zs = blockIdx.z % nsplit;
    const int m0 = blockIdx.y * BM;
    const int n0 = blockIdx.x * BN;

    float acc[4][4][4];
#pragma unroll
    for (int i = 0; i < 4; i++)
#pragma unroll
        for (int j = 0; j < 4; j++)
#pragma unroll
            for (int c = 0; c < 4; c++) acc[i][j][c] = 0.0f;

    // ldmatrix addresses (bytes): A rows = m, B rows = n; col in halves
    const int lrF = lane & 15;
    const int lcF = (lane >> 4) * 8;
    const uint32_t baseU  = smem_u32(smem);
    const uint32_t stageB = (uint32_t)(STAGEF * 2);
    uint32_t aAddr[4], bAddr[2];
#pragma unroll
    for (int mt = 0; mt < 4; mt++)
        aAddr[mt] = baseU + (uint32_t)(((wm * 64 + mt * 16 + lrF) * HSTR + lcF) * 2);
#pragma unroll
    for (int p = 0; p < 2; p++)
        bAddr[p] = baseU + (uint32_t)((BM * HSTR + (wn * 32 + p * 16 + lrF) * HSTR + lcF) * 2);

    const int S = K / BK;

    // loader: task = one 16B chunk (8 halves / 8 floats src) of a tile row.
    // phase ph in {0,1}: idx = tid + ph*256 over 512 tasks: row=idx&127, sg=idx>>7.
    uint4 sreg[4];   // [0..1]=A phases, [2..3]=B phases

    auto ldg_stage = [&](int s) {
        const int k0 = s * BK;
#pragma unroll
        for (int ph = 0; ph < 2; ph++) {
            const int idx = tid + ph * 256;
            const int row = idx & 127, sg = idx >> 7;   // sg: 0..3 (8-elem units)
            if (ROUND) {
                const float* ap = (const float*)Av + zh * aH + zs * aS
                                + (long long)(m0 + row) * lda + k0 + sg * 8;
                float4 v0 = *(const float4*)ap;
                float4 v1 = *(const float4*)(ap + 4);
                for (int p = 1; p < nparts; p++) {
                    const float* pp = ap + (long long)p * pStride;
                    float4 w0 = *(const float4*)pp;
                    float4 w1 = *(const float4*)(pp + 4);
                    v0.x += w0.x; v0.y += w0.y; v0.z += w0.z; v0.w += w0.w;
                    v1.x += w1.x; v1.y += w1.y; v1.z += w1.z; v1.w += w1.w;
                }
                sreg[ph] = make_uint4(packh2(v0.x, v0.y), packh2(v0.z, v0.w),
                                      packh2(v1.x, v1.y), packh2(v1.z, v1.w));
                const float* bp = (const float*)Bv + zh * bH + zs * bS
                                + (long long)(n0 + row) * ldb + k0 + sg * 8;
                float4 u0 = *(const float4*)bp;
                float4 u1 = *(const float4*)(bp + 4);
                sreg[2 + ph] = make_uint4(packh2(u0.x, u0.y), packh2(u0.z, u0.w),
                                          packh2(u1.x, u1.y), packh2(u1.z, u1.w));
            } else {
                const __half* ap = (const __half*)Av + zh * aH + zs * aS
                                 + (long long)(m0 + row) * lda + k0 + sg * 8;
                sreg[ph] = *(const uint4*)ap;
                const __half* bp = (const __half*)Bv + zh * bH + zs * bS
                                 + (long long)(n0 + row) * ldb + k0 + sg * 8;
                sreg[2 + ph] = *(const uint4*)bp;
            }
        }
    };
    auto sts_stage = [&](int bu) {
        __half* As = smem + bu * STAGEF;
        __half* Bs = As + BM * HSTR;
#pragma unroll
        for (int ph = 0; ph < 2; ph++) {
            const int idx = tid + ph * 256;
            const int row = idx & 127, sg = idx >> 7;
            *(uint4*)&As[row * HSTR + sg * 8] = sreg[ph];
            *(uint4*)&Bs[row * HSTR + sg * 8] = sreg[2 + ph];
        }
    };
    auto compute = [&](int bu) {
        const uint32_t off = bu * stageB;
#pragma unroll
        for (int ks = 0; ks < 2; ks++) {          // two k16 steps per stage
            const uint32_t kb = (uint32_t)(ks * 32) + off;   // 16 halves = 32 B
            uint32_t af[4][4], bq[2][4];
#pragma unroll
            for (int mt = 0; mt < 4; mt++) ldsm_x4(af[mt], aAddr[mt] + kb);
#pragma unroll
            for (int p = 0; p < 2; p++)  ldsm_x4(bq[p], bAddr[p] + kb);
#pragma unroll
            for (int mt = 0; mt < 4; mt++)
#pragma unroll
                for (int nt = 0; nt < 4; nt++)
                    mma_f16(acc[mt][nt], af[mt],
                            bq[nt >> 1][nt & 1], bq[nt >> 1][2 + (nt & 1)]);
        }
    };

    ldg_stage(0);
    sts_stage(0);
    for (int s = 0; s < S; s++) {
        __syncthreads();
        if (s + 1 < S) ldg_stage(s + 1);
        compute(s & 1);
        if (s + 1 < S) sts_stage((s + 1) & 1);
    }

    // ---------------- epilogues ----------------
    if (epi == 5) {
        // softmax over the 64 frame-rows of this thread's wm-half (one video),
        // transposed store to Wt[h][bt][av], half, with /16 and /128 folded in.
#pragma unroll
        for (int nt = 0; nt < 4; nt++) {
#pragma unroll
            for (int p = 0; p < 2; p++) {
                float m = -1e30f;
#pragma unroll
                for (int mt = 0; mt < 4; mt++)
                    m = fmaxf(m, fmaxf(acc[mt][nt][p], acc[mt][nt][p + 2]));
                m = fmaxf(m, __shfl_xor_sync(0xffffffffu, m, 4));
                m = fmaxf(m, __shfl_xor_sync(0xffffffffu, m, 8));
                m = fmaxf(m, __shfl_xor_sync(0xffffffffu, m, 16));
                float sum = 0.0f;
#pragma unroll
                for (int mt = 0; mt < 4; mt++) {
                    float e0 = __expf((acc[mt][nt][p]     - m) * 0.0625f);
                    float e1 = __expf((acc[mt][nt][p + 2] - m) * 0.0625f);
                    acc[mt][nt][p]     = e0;
                    acc[mt][nt][p + 2] = e1;
                    sum += e0 + e1;
                }
                sum += __shfl_xor_sync(0xffffffffu, sum, 4);
                sum += __shfl_xor_sync(0xffffffffu, sum, 8);
                sum += __shfl_xor_sync(0xffffffffu, sum, 16);
                const float inv = 1.0f / (128.0f * sum);
                const int bt = n0 + wn * 32 + nt * 8 + 2 * tig + p;
                const int rb2 = m0 + wm * 64 + gid;
                __half* Wc = (__half*)Dv + (long long)zh * dH + (long long)bt * MVID;
#pragma unroll
                for (int mt = 0; mt < 4; mt++) {
                    Wc[rb2 + mt * 16    ] = __float2half_rn(acc[mt][nt][p]     * inv);
                    Wc[rb2 + mt * 16 + 8] = __float2half_rn(acc[mt][nt][p + 2] * inv);
                }
            }
        }
        return;
    }

#pragma unroll
    for (int mt = 0; mt < 4; mt++) {
#pragma unroll
        for (int nt = 0; nt < 4; nt++) {
            const int r0 = m0 + wm * 64 + mt * 16 + gid;
            const int cN = n0 + wn * 32 + nt * 8 + 2 * tig;
#pragma unroll
            for (int half = 0; half < 2; half++) {
                const int r = r0 + half * 8;
                float x = acc[mt][nt][half * 2 + 0];
                float y = acc[mt][nt][half * 2 + 1];
                if (epi == 0) {
                    float2 o = make_float2(x * scale + bias[cN],
                                           y * scale + bias[cN + 1]);
                    *(float2*)&((float*)Dv)[dH * zh + (long long)r * ldd + cN] = o;
                } else if (epi == 4) {
                    __half2 h = __floats2half2_rn(x * scale + bias[cN],
                                                  y * scale + bias[cN + 1]);
                    *(__half2*)&((__half*)Dv)[dH * zh + (long long)r * ldd + cN] = h;
                } else if (epi == 1) {
                    // Vt: n = h*256 + d  ->  D[n*MVID + m], half
                    ((__half*)Dv)[(long long)(cN    ) * MVID + r] = __float2half_rn(x);
                    ((__half*)Dv)[(long long)(cN + 1) * MVID + r] = __float2half_rn(y);
                } else {
                    // attn scatter: m = b*32+t, n = d (torch reshape layout), fp32
                    long long addr = (long long)zs * pStride
                                   + (long long)(r >> 5) * 16384
                                   + (long long)zh * 8192
                                   + (r & 31) * 256 + cN;
                    *(float2*)&((float*)Dv)[addr] = make_float2(x, y);
                }
            }
        }
    }
}

// ---------------------------------------------------------------------------
extern "C" void kernel_launch(void* const* d_in, const int* in_sizes, int n_in,
                              void* d_out, int out_size)
{
    const float* text  = (const float*)d_in[0];
    const float* video = (const float*)d_in[1];
    const float* Wq = (const float*)d_in[2];
    const float* bq = (const float*)d_in[3];
    const float* Wk = (const float*)d_in[4];
    const float* bk = (const float*)d_in[5];
    const float* Wv = (const float*)d_in[6];
    const float* bv = (const float*)d_in[7];
    const float* Wo = (const float*)d_in[8];
    const float* bo = (const float*)d_in[9];
    float* out = (float*)d_out;

    __half *Qp, *Kp, *Vtp, *Wtp;
    float* Pp;
    cudaGetSymbolAddress((void**)&Qp,  g_Qh);
    cudaGetSymbolAddress((void**)&Kp,  g_Kh);
    cudaGetSymbolAddress((void**)&Vtp, g_Vth);
    cudaGetSymbolAddress((void**)&Wtp, g_Wth);
    cudaGetSymbolAddress((void**)&Pp,  g_part);

    dim3 t(256);

    // Q/K projections -> half (epi4); V projection -> Vt half transpose (epi1)
    gemm_mma<true><<<dim3(4, 16, 1), t>>>(text, 512, 0, 0,  Wq, 512, 0, 0,
        bq, Qp, 512, 1, 1, 0, 4, 512, 0, 1.0f);
    gemm_mma<true><<<dim3(4, 64, 1), t>>>(video, 512, 0, 0, Wk, 512, 0, 0,
        bk, Kp, 512, 1, 1, 0, 4, 512, 0, 1.0f);
    gemm_mma<true><<<dim3(4, 64, 1), t>>>(video, 512, 0, 0, Wv, 512, 0, 0,
        bv, Vtp, 512, 1, 1, 0, 1, 0, 0, 1.0f);

    // Logits + fused softmax (epi5): writes Wt[h][bt][av] (half)
    gemm_mma<false><<<dim3(16, 64, 2), t>>>(Kp, 512, 256, 0, Qp, 512, 256, 0,
        nullptr, Wtp, 256, 1, 1, 0, 5, 0, (long long)MTXT * MVID, 1.0f);

    // Attention: D[bt, d] = sum_av Wt[bt,av] * Vt[d,av], split-K x4 (epi3)
    gemm_mma<false><<<dim3(2, 16, 2 * NSPLIT), t>>>(Wtp, MVID,
        (long long)MTXT * MVID, KSPL,
        Vtp, MVID, (long long)HD * MVID, KSPL,
        nullptr, Pp, KSPL, NSPLIT, 1, (long long)MTXT * E, 3, 0, 0, 1.0f);

    // Output projection, summing the 4 split-K partials during A-load (epi0)
    gemm_mma<true><<<dim3(4, 16, 1), t>>>(Pp, 512, 0, 0, Wo, 512, 0, 0,
        bo, out, 512, 1, NSPLIT, (long long)MTXT * E, 0, 512, 0, 1.0f);
}

// round 14
// speedup vs baseline: 1.8798x; 1.7607x over previous
#include <cuda_runtime.h>
#include <cuda_fp16.h>
#include <cstdint>

#define E    512
#define HD   256
#define MTXT 2048
#define MVID 8192
#define NSPLIT 4
#define KSPL  2048

#define BM 128
#define BN 128
#define BK 32        // k-halves per stage (2 x k16 mma steps)
#define HSTR 40      // smem row stride in halves (ldmatrix conflict-free)
#define STAGEH ((BM + BN) * HSTR)    // 10240 halves
#define STAGEB (STAGEH * 2)          // 20480 B
#define NSTAGE 3
#define SMEM_BYTES (NSTAGE * STAGEB) // 61440 B

// ---------------- device scratch ----------------
__device__ __half g_th[(long long)MTXT * E];
__device__ __half g_vh[(long long)MVID * E];
__device__ __half g_Wqh[E * E], g_Wkh[E * E], g_Wvh[E * E], g_Woh[E * E];
__device__ __half g_Qh[(long long)MTXT * E];
__device__ __half g_Kh[(long long)MVID * E];
__device__ __half g_Vth[2ll * HD * MVID];
__device__ __half g_Wth[2ll * MTXT * MVID];
__device__ float  g_part[(long long)NSPLIT * MTXT * E];
__device__ __half g_Ah[(long long)MTXT * E];

__device__ __forceinline__ uint32_t smem_u32(const void* p) {
    uint32_t a;
    asm("{ .reg .u64 t; cvta.to.shared.u64 t, %1; cvt.u32.u64 %0, t; }" : "=r"(a) : "l"(p));
    return a;
}
__device__ __forceinline__ uint32_t packh2(float a, float b) {
    __half2 h = __floats2half2_rn(a, b);
    return *reinterpret_cast<uint32_t*>(&h);
}
__device__ __forceinline__ void cpa16(uint32_t d, const void* g) {
    asm volatile("cp.async.cg.shared.global [%0], [%1], 16;" :: "r"(d), "l"(g));
}
#define CP_COMMIT() asm volatile("cp.async.commit_group;" ::: "memory")
#define CP_WAIT1()  asm volatile("cp.async.wait_group 1;" ::: "memory")
#define CP_WAIT0()  asm volatile("cp.async.wait_group 0;" ::: "memory")

__device__ __forceinline__ void mma_f16(float* c, const uint32_t* a,
                                        uint32_t b0, uint32_t b1) {
    asm volatile(
        "mma.sync.aligned.m16n8k16.row.col.f32.f16.f16.f32 "
        "{%0,%1,%2,%3}, {%4,%5,%6,%7}, {%8,%9}, {%0,%1,%2,%3};"
        : "+f"(c[0]), "+f"(c[1]), "+f"(c[2]), "+f"(c[3])
        : "r"(a[0]), "r"(a[1]), "r"(a[2]), "r"(a[3]), "r"(b0), "r"(b1));
}
__device__ __forceinline__ void ldsm_x4(uint32_t* r, uint32_t addr) {
    asm volatile("ldmatrix.sync.aligned.m8n8.x4.shared.b16 {%0,%1,%2,%3}, [%4];"
        : "=r"(r[0]), "=r"(r[1]), "=r"(r[2]), "=r"(r[3]) : "r"(addr));
}

// ---------------------------------------------------------------------------
// fp16 mma.sync GEMM (fp32 accum), cp.async 3-stage pipeline.
// D[m,n] = sum_k A[m,k] * B[n,k]   (both K-major, fp16)
// epi: 0 = bias+store fp32 (final)      1 = Vt transpose store (half)
//      3 = attn scatter fp32 (reshape)  4 = bias+store half (Q/K)
//      5 = fused softmax-over-frames -> Wt[h][bt][av] (half, /16, /128)
// ---------------------------------------------------------------------------
__global__ __launch_bounds__(256, 2) void gemm_h(
    const __half* __restrict__ A, int lda, long long aH, long long aS,
    const __half* __restrict__ B, int ldb, long long bH, long long bS,
    const float* __restrict__ bias, void* __restrict__ Dv,
    int K, int nsplit, long long pStride,
    int epi, int ldd, long long dH, float scale)
{
    extern __shared__ __half smem[];

    const int tid  = threadIdx.x;
    const int warp = tid >> 5;
    const int lane = tid & 31;
    const int gid  = lane >> 2;
    const int tig  = lane & 3;
    const int wm   = warp & 1;
    const int wn   = warp >> 1;

    const int zh = blockIdx.z / nsplit;
    const int zs = blockIdx.z % nsplit;
    const int m0 = blockIdx.y * BM;
    const int n0 = blockIdx.x * BN;
    const __half* Ab = A + zh * aH + zs * aS;
    const __half* Bb = B + zh * bH + zs * bS;

    float acc[4][4][4];
#pragma unroll
    for (int i = 0; i < 4; i++)
#pragma unroll
        for (int j = 0; j < 4; j++)
#pragma unroll
            for (int c = 0; c < 4; c++) acc[i][j][c] = 0.0f;

    // ---- loader: 4 cp.async 16B per thread per stage, pointers hoisted ----
    const int lrow = tid >> 2;            // 0..63
    const int lch  = (tid & 3) * 16;      // byte chunk in row
    const uint32_t baseU = smem_u32(smem);
    const char* gA0 = (const char*)(Ab + (long long)(m0 + lrow) * lda) + lch;
    const char* gA1 = (const char*)(Ab + (long long)(m0 + lrow + 64) * lda) + lch;
    const char* gB0 = (const char*)(Bb + (long long)(n0 + lrow) * ldb) + lch;
    const char* gB1 = (const char*)(Bb + (long long)(n0 + lrow + 64) * ldb) + lch;
    const uint32_t sA0 = baseU + (uint32_t)(lrow * 80 + lch);
    const uint32_t sA1 = sA0 + 64 * 80;
    const uint32_t sB0 = baseU + (uint32_t)(BM * 80 + lrow * 80 + lch);
    const uint32_t sB1 = sB0 + 64 * 80;

    auto issue = [&](int s, int bu) {
        const int kB = s * (BK * 2);          // 64 bytes per stage
        const uint32_t off = (uint32_t)(bu * STAGEB);
        cpa16(sA0 + off, gA0 + kB);
        cpa16(sA1 + off, gA1 + kB);
        cpa16(sB0 + off, gB0 + kB);
        cpa16(sB1 + off, gB1 + kB);
        CP_COMMIT();
    };

    // ---- fragment addresses ----
    const int lrF = lane & 15;
    const int lcF = (lane >> 4) * 8;
    uint32_t aAddr[4], bAddr[2];
#pragma unroll
    for (int mt = 0; mt < 4; mt++)
        aAddr[mt] = baseU + (uint32_t)(((wm * 64 + mt * 16 + lrF) * HSTR + lcF) * 2);
#pragma unroll
    for (int p = 0; p < 2; p++)
        bAddr[p] = baseU + (uint32_t)((BM * HSTR + (wn * 32 + p * 16 + lrF) * HSTR + lcF) * 2);

    auto compute = [&](int st) {
        const uint32_t off = (uint32_t)(st * STAGEB);
#pragma unroll
        for (int ks = 0; ks < 2; ks++) {
            const uint32_t kb = (uint32_t)(ks * 32) + off;
            uint32_t af[4][4], bq[2][4];
#pragma unroll
            for (int mt = 0; mt < 4; mt++) ldsm_x4(af[mt], aAddr[mt] + kb);
#pragma unroll
            for (int p = 0; p < 2; p++)  ldsm_x4(bq[p], bAddr[p] + kb);
#pragma unroll
            for (int mt = 0; mt < 4; mt++)
#pragma unroll
                for (int nt = 0; nt < 4; nt++)
                    mma_f16(acc[mt][nt], af[mt],
                            bq[nt >> 1][nt & 1], bq[nt >> 1][2 + (nt & 1)]);
        }
    };

    const int S = K / BK;
    issue(0, 0);
    issue(1, 1);
    int st = 0;
    for (int s = 0; s < S; s++) {
        if (s + 1 < S) CP_WAIT1(); else CP_WAIT0();
        __syncthreads();
        if (s + 2 < S) issue(s + 2, (st + 2) % NSTAGE);
        compute(st);
        st = (st + 1) % NSTAGE;
    }

    // ---------------- epilogues ----------------
    if (epi == 5) {
        // softmax over the 64 frame-rows of this thread's wm-half (one video),
        // transposed store to Wt[h][bt][av], half, with /16 and /128 folded in.
#pragma unroll
        for (int nt = 0; nt < 4; nt++) {
#pragma unroll
            for (int p = 0; p < 2; p++) {
                float m = -1e30f;
#pragma unroll
                for (int mt = 0; mt < 4; mt++)
                    m = fmaxf(m, fmaxf(acc[mt][nt][p], acc[mt][nt][p + 2]));
                m = fmaxf(m, __shfl_xor_sync(0xffffffffu, m, 4));
                m = fmaxf(m, __shfl_xor_sync(0xffffffffu, m, 8));
                m = fmaxf(m, __shfl_xor_sync(0xffffffffu, m, 16));
                float sum = 0.0f;
#pragma unroll
                for (int mt = 0; mt < 4; mt++) {
                    float e0 = __expf((acc[mt][nt][p]     - m) * 0.0625f);
                    float e1 = __expf((acc[mt][nt][p + 2] - m) * 0.0625f);
                    acc[mt][nt][p]     = e0;
                    acc[mt][nt][p + 2] = e1;
                    sum += e0 + e1;
                }
                sum += __shfl_xor_sync(0xffffffffu, sum, 4);
                sum += __shfl_xor_sync(0xffffffffu, sum, 8);
                sum += __shfl_xor_sync(0xffffffffu, sum, 16);
                const float inv = 1.0f / (128.0f * sum);
                const int bt = n0 + wn * 32 + nt * 8 + 2 * tig + p;
                const int rb2 = m0 + wm * 64 + gid;
                __half* Wc = (__half*)Dv + (long long)zh * dH + (long long)bt * MVID;
#pragma unroll
                for (int mt = 0; mt < 4; mt++) {
                    Wc[rb2 + mt * 16    ] = __float2half_rn(acc[mt][nt][p]     * inv);
                    Wc[rb2 + mt * 16 + 8] = __float2half_rn(acc[mt][nt][p + 2] * inv);
                }
            }
        }
        return;
    }

#pragma unroll
    for (int mt = 0; mt < 4; mt++) {
#pragma unroll
        for (int nt = 0; nt < 4; nt++) {
            const int r0 = m0 + wm * 64 + mt * 16 + gid;
            const int cN = n0 + wn * 32 + nt * 8 + 2 * tig;
#pragma unroll
            for (int half = 0; half < 2; half++) {
                const int r = r0 + half * 8;
                float x = acc[mt][nt][half * 2 + 0];
                float y = acc[mt][nt][half * 2 + 1];
                if (epi == 0) {
                    float2 o = make_float2(x * scale + bias[cN],
                                           y * scale + bias[cN + 1]);
                    *(float2*)&((float*)Dv)[dH * zh + (long long)r * ldd + cN] = o;
                } else if (epi == 4) {
                    __half2 h = __floats2half2_rn(x * scale + bias[cN],
                                                  y * scale + bias[cN + 1]);
                    *(__half2*)&((__half*)Dv)[dH * zh + (long long)r * ldd + cN] = h;
                } else if (epi == 1) {
                    ((__half*)Dv)[(long long)(cN    ) * MVID + r] = __float2half_rn(x);
                    ((__half*)Dv)[(long long)(cN + 1) * MVID + r] = __float2half_rn(y);
                } else {
                    long long addr = (long long)zs * pStride
                                   + (long long)(r >> 5) * 16384
                                   + (long long)zh * 8192
                                   + (r & 31) * 256 + cN;
                    *(float2*)&((float*)Dv)[addr] = make_float2(x, y);
                }
            }
        }
    }
}

// ---------------------------------------------------------------------------
// fp32 -> fp16 converter (vectorized, 8 elems/thread)
// ---------------------------------------------------------------------------
__global__ void cvtf2h(const float* __restrict__ s, __half* __restrict__ d, int n8)
{
    int i = blockIdx.x * blockDim.x + threadIdx.x;
    if (i < n8) {
        const float4* sp = (const float4*)s + 2 * (long long)i;
        float4 a = sp[0], b = sp[1];
        uint4 o;
        o.x = packh2(a.x, a.y); o.y = packh2(a.z, a.w);
        o.z = packh2(b.x, b.y); o.w = packh2(b.z, b.w);
        *((uint4*)d + i) = o;
    }
}

// Sum the 4 split-K fp32 partials and convert to fp16 (4 elems/thread)
__global__ void sum4cvt(const float* __restrict__ p, __half* __restrict__ d, int n4)
{
    int i = blockIdx.x * blockDim.x + threadIdx.x;
    if (i < n4) {
        const long long st = (long long)MTXT * E / 4;
        float4 v = *((const float4*)p + i);
        float4 b1 = *((const float4*)p + st + i);
        float4 b2 = *((const float4*)p + 2 * st + i);
        float4 b3 = *((const float4*)p + 3 * st + i);
        v.x += b1.x + b2.x + b3.x;
        v.y += b1.y + b2.y + b3.y;
        v.z += b1.z + b2.z + b3.z;
        v.w += b1.w + b2.w + b3.w;
        uint2 o;
        o.x = packh2(v.x, v.y); o.y = packh2(v.z, v.w);
        *((uint2*)d + i) = o;
    }
}

// ---------------------------------------------------------------------------
extern "C" void kernel_launch(void* const* d_in, const int* in_sizes, int n_in,
                              void* d_out, int out_size)
{
    const float* text  = (const float*)d_in[0];
    const float* video = (const float*)d_in[1];
    const float* Wq = (const float*)d_in[2];
    const float* bq = (const float*)d_in[3];
    const float* Wk = (const float*)d_in[4];
    const float* bk = (const float*)d_in[5];
    const float* Wv = (const float*)d_in[6];
    const float* bv = (const float*)d_in[7];
    const float* Wo = (const float*)d_in[8];
    const float* bo = (const float*)d_in[9];
    float* out = (float*)d_out;

    __half *thp, *vhp, *Wqh, *Wkh, *Wvh, *Woh, *Qp, *Kp, *Vtp, *Wtp, *Ahp;
    float* Pp;
    cudaGetSymbolAddress((void**)&thp, g_th);
    cudaGetSymbolAddress((void**)&vhp, g_vh);
    cudaGetSymbolAddress((void**)&Wqh, g_Wqh);
    cudaGetSymbolAddress((void**)&Wkh, g_Wkh);
    cudaGetSymbolAddress((void**)&Wvh, g_Wvh);
    cudaGetSymbolAddress((void**)&Woh, g_Woh);
    cudaGetSymbolAddress((void**)&Qp,  g_Qh);
    cudaGetSymbolAddress((void**)&Kp,  g_Kh);
    cudaGetSymbolAddress((void**)&Vtp, g_Vth);
    cudaGetSymbolAddress((void**)&Wtp, g_Wth);
    cudaGetSymbolAddress((void**)&Pp,  g_part);
    cudaGetSymbolAddress((void**)&Ahp, g_Ah);

    cudaFuncSetAttribute(gemm_h,
                         cudaFuncAttributeMaxDynamicSharedMemorySize, SMEM_BYTES);

    dim3 t(256);

    // ---- input conversion to fp16 ----
    cvtf2h<<<512,  256>>>(text,  thp, MTXT * E / 8);
    cvtf2h<<<2048, 256>>>(video, vhp, MVID * E / 8);
    cvtf2h<<<128,  256>>>(Wq, Wqh, E * E / 8);
    cvtf2h<<<128,  256>>>(Wk, Wkh, E * E / 8);
    cvtf2h<<<128,  256>>>(Wv, Wvh, E * E / 8);
    cvtf2h<<<128,  256>>>(Wo, Woh, E * E / 8);

    // ---- projections ----
    gemm_h<<<dim3(4, 16, 1), t, SMEM_BYTES>>>(thp, 512, 0, 0, Wqh, 512, 0, 0,
        bq, Qp, 512, 1, 0, 4, 512, 0, 1.0f);
    gemm_h<<<dim3(4, 64, 1), t, SMEM_BYTES>>>(vhp, 512, 0, 0, Wkh, 512, 0, 0,
        bk, Kp, 512, 1, 0, 4, 512, 0, 1.0f);
    gemm_h<<<dim3(4, 64, 1), t, SMEM_BYTES>>>(vhp, 512, 0, 0, Wvh, 512, 0, 0,
        bv, Vtp, 512, 1, 0, 1, 0, 0, 1.0f);

    // ---- logits + fused softmax -> Wt[h][bt][av] ----
    gemm_h<<<dim3(16, 64, 2), t, SMEM_BYTES>>>(Kp, 512, 256, 0, Qp, 512, 256, 0,
        nullptr, Wtp, 256, 1, 0, 5, 0, (long long)MTXT * MVID, 1.0f);

    // ---- attention: split-K x4, fp32 partials ----
    gemm_h<<<dim3(2, 16, 2 * NSPLIT), t, SMEM_BYTES>>>(Wtp, MVID,
        (long long)MTXT * MVID, KSPL,
        Vtp, MVID, (long long)HD * MVID, KSPL,
        nullptr, Pp, KSPL, NSPLIT, (long long)MTXT * E, 3, 0, 0, 1.0f);

    // ---- sum partials + convert ----
    sum4cvt<<<1024, 256>>>(Pp, Ahp, MTXT * E / 4);

    // ---- output projection ----
    gemm_h<<<dim3(4, 16, 1), t, SMEM_BYTES>>>(Ahp, 512, 0, 0, Woh, 512, 0, 0,
        bo, out, 512, 1, 0, 0, 512, 0, 1.0f);
}

// round 15
// speedup vs baseline: 1.8829x; 1.0017x over previous
#include <cuda_runtime.h>
#include <cuda_fp16.h>
#include <cstdint>

#define E    512
#define HD   256
#define MTXT 2048
#define MVID 8192
#define NSPLIT 4
#define KSPL  2048

#define BM 128
#define BN 128
#define BK 32        // k-halves per stage (2 x k16 mma steps)
#define HSTR 40      // smem row stride in halves (ldmatrix conflict-free)
#define STAGEH ((BM + BN) * HSTR)    // 10240 halves
#define STAGEB (STAGEH * 2)          // 20480 B
#define NSTAGE 3
#define SMEM_BYTES (NSTAGE * STAGEB) // 61440 B

// ---------------- device scratch ----------------
__device__ __half g_th[(long long)MTXT * E];
__device__ __half g_vh[(long long)MVID * E];
__device__ __half g_Wqh[E * E], g_Wkh[E * E], g_Wvh[E * E], g_Woh[E * E];
__device__ __half g_Qh[(long long)MTXT * E];
__device__ __half g_Kh[(long long)MVID * E];
__device__ __half g_Vth[2ll * HD * MVID];
__device__ __half g_Wth[2ll * MTXT * MVID];
__device__ float  g_part[(long long)NSPLIT * MTXT * E];
__device__ __half g_Ah[(long long)MTXT * E];

__device__ __forceinline__ uint32_t smem_u32(const void* p) {
    uint32_t a;
    asm("{ .reg .u64 t; cvta.to.shared.u64 t, %1; cvt.u32.u64 %0, t; }" : "=r"(a) : "l"(p));
    return a;
}
__device__ __forceinline__ uint32_t packh2(float a, float b) {
    __half2 h = __floats2half2_rn(a, b);
    return *reinterpret_cast<uint32_t*>(&h);
}
__device__ __forceinline__ void cpa16(uint32_t d, const void* g) {
    asm volatile("cp.async.cg.shared.global [%0], [%1], 16;" :: "r"(d), "l"(g));
}
#define CP_COMMIT() asm volatile("cp.async.commit_group;" ::: "memory")
#define CP_WAIT1()  asm volatile("cp.async.wait_group 1;" ::: "memory")
#define CP_WAIT0()  asm volatile("cp.async.wait_group 0;" ::: "memory")

__device__ __forceinline__ void mma_f16(float* c, const uint32_t* a,
                                        uint32_t b0, uint32_t b1) {
    asm volatile(
        "mma.sync.aligned.m16n8k16.row.col.f32.f16.f16.f32 "
        "{%0,%1,%2,%3}, {%4,%5,%6,%7}, {%8,%9}, {%0,%1,%2,%3};"
        : "+f"(c[0]), "+f"(c[1]), "+f"(c[2]), "+f"(c[3])
        : "r"(a[0]), "r"(a[1]), "r"(a[2]), "r"(a[3]), "r"(b0), "r"(b1));
}
__device__ __forceinline__ void ldsm_x4(uint32_t* r, uint32_t addr) {
    asm volatile("ldmatrix.sync.aligned.m8n8.x4.shared.b16 {%0,%1,%2,%3}, [%4];"
        : "=r"(r[0]), "=r"(r[1]), "=r"(r[2]), "=r"(r[3]) : "r"(addr));
}

// ---------------------------------------------------------------------------
// fp16 mma.sync GEMM (fp32 accum), cp.async 3-stage pipeline.
// 128 threads (4 warps), block tile 128x128, warp tile 64x64.
// D[m,n] = sum_k A[m,k] * B[n,k]   (both K-major, fp16)
// epi: 0 = bias+store fp32 (final)      1 = Vt transpose store (half)
//      3 = attn scatter fp32 (reshape)  4 = bias+store half (Q/K)
//      5 = fused softmax-over-frames -> Wt[h][bt][av] (half, /16, /128)
// ---------------------------------------------------------------------------
__global__ __launch_bounds__(128, 2) void gemm_h(
    const __half* __restrict__ A, int lda, long long aH, long long aS,
    const __half* __restrict__ B, int ldb, long long bH, long long bS,
    const float* __restrict__ bias, void* __restrict__ Dv,
    int K, int nsplit, long long pStride,
    int epi, int ldd, long long dH, float scale)
{
    extern __shared__ __half smem[];

    const int tid  = threadIdx.x;
    const int warp = tid >> 5;
    const int lane = tid & 31;
    const int gid  = lane >> 2;
    const int tig  = lane & 3;
    const int wm   = warp & 1;     // 2 m-groups of 64
    const int wn   = warp >> 1;    // 2 n-groups of 64

    const int zh = blockIdx.z / nsplit;
    const int zs = blockIdx.z % nsplit;
    const int m0 = blockIdx.y * BM;
    const int n0 = blockIdx.x * BN;
    const __half* Ab = A + zh * aH + zs * aS;
    const __half* Bb = B + zh * bH + zs * bS;

    float acc[4][8][4];
#pragma unroll
    for (int i = 0; i < 4; i++)
#pragma unroll
        for (int j = 0; j < 8; j++)
#pragma unroll
            for (int c = 0; c < 4; c++) acc[i][j][c] = 0.0f;

    // ---- loader: 8 cp.async 16B per thread per stage ----
    const int lrow = tid >> 2;            // 0..31
    const int lch  = (tid & 3) * 16;      // byte chunk in row
    const uint32_t baseU = smem_u32(smem);
    const char* gA = (const char*)(Ab + (long long)(m0 + lrow) * lda) + lch;
    const char* gB = (const char*)(Bb + (long long)(n0 + lrow) * ldb) + lch;
    const long long aStep = (long long)lda * 32 * 2;   // 32 rows in bytes
    const long long bStep = (long long)ldb * 32 * 2;
    const uint32_t sA = baseU + (uint32_t)(lrow * 80 + lch);
    const uint32_t sB = baseU + (uint32_t)(BM * 80 + lrow * 80 + lch);

    auto issue = [&](int s, int bu) {
        const int kB = s * (BK * 2);          // 64 bytes per stage
        const uint32_t off = (uint32_t)(bu * STAGEB);
#pragma unroll
        for (int i = 0; i < 4; i++)
            cpa16(sA + off + (uint32_t)(i * 32 * 80), gA + i * aStep + kB);
#pragma unroll
        for (int i = 0; i < 4; i++)
            cpa16(sB + off + (uint32_t)(i * 32 * 80), gB + i * bStep + kB);
        CP_COMMIT();
    };

    // ---- fragment addresses ----
    const int lrF = lane & 15;
    const int lcF = (lane >> 4) * 8;
    uint32_t aAddr[4], bAddr[4];
#pragma unroll
    for (int mt = 0; mt < 4; mt++)
        aAddr[mt] = baseU + (uint32_t)(((wm * 64 + mt * 16 + lrF) * HSTR + lcF) * 2);
#pragma unroll
    for (int p = 0; p < 4; p++)
        bAddr[p] = baseU + (uint32_t)((BM * HSTR + (wn * 64 + p * 16 + lrF) * HSTR + lcF) * 2);

    auto compute = [&](int st) {
        const uint32_t off = (uint32_t)(st * STAGEB);
#pragma unroll
        for (int ks = 0; ks < 2; ks++) {
            const uint32_t kb = (uint32_t)(ks * 32) + off;
            uint32_t af[4][4], bq[4][4];
#pragma unroll
            for (int mt = 0; mt < 4; mt++) ldsm_x4(af[mt], aAddr[mt] + kb);
#pragma unroll
            for (int p = 0; p < 4; p++)  ldsm_x4(bq[p], bAddr[p] + kb);
#pragma unroll
            for (int mt = 0; mt < 4; mt++)
#pragma unroll
                for (int nt = 0; nt < 8; nt++)
                    mma_f16(acc[mt][nt], af[mt],
                            bq[nt >> 1][nt & 1], bq[nt >> 1][2 + (nt & 1)]);
        }
    };

    const int S = K / BK;
    issue(0, 0);
    issue(1, 1);
    int st = 0;
    for (int s = 0; s < S; s++) {
        if (s + 1 < S) CP_WAIT1(); else CP_WAIT0();
        __syncthreads();
        if (s + 2 < S) issue(s + 2, (st + 2) % NSTAGE);
        compute(st);
        st = (st + 1) % NSTAGE;
    }

    // ---------------- epilogues ----------------
    if (epi == 5) {
        // softmax over the 64 frame-rows of this thread's wm-half (one video),
        // transposed store to Wt[h][bt][av], half, with /16 and /128 folded in.
#pragma unroll
        for (int nt = 0; nt < 8; nt++) {
#pragma unroll
            for (int p = 0; p < 2; p++) {
                float m = -1e30f;
#pragma unroll
                for (int mt = 0; mt < 4; mt++)
                    m = fmaxf(m, fmaxf(acc[mt][nt][p], acc[mt][nt][p + 2]));
                m = fmaxf(m, __shfl_xor_sync(0xffffffffu, m, 4));
                m = fmaxf(m, __shfl_xor_sync(0xffffffffu, m, 8));
                m = fmaxf(m, __shfl_xor_sync(0xffffffffu, m, 16));
                float sum = 0.0f;
#pragma unroll
                for (int mt = 0; mt < 4; mt++) {
                    float e0 = __expf((acc[mt][nt][p]     - m) * 0.0625f);
                    float e1 = __expf((acc[mt][nt][p + 2] - m) * 0.0625f);
                    acc[mt][nt][p]     = e0;
                    acc[mt][nt][p + 2] = e1;
                    sum += e0 + e1;
                }
                sum += __shfl_xor_sync(0xffffffffu, sum, 4);
                sum += __shfl_xor_sync(0xffffffffu, sum, 8);
                sum += __shfl_xor_sync(0xffffffffu, sum, 16);
                const float inv = 1.0f / (128.0f * sum);
                const int bt = n0 + wn * 64 + nt * 8 + 2 * tig + p;
                const int rb2 = m0 + wm * 64 + gid;
                __half* Wc = (__half*)Dv + (long long)zh * dH + (long long)bt * MVID;
#pragma unroll
                for (int mt = 0; mt < 4; mt++) {
                    Wc[rb2 + mt * 16    ] = __float2half_rn(acc[mt][nt][p]     * inv);
                    Wc[rb2 + mt * 16 + 8] = __float2half_rn(acc[mt][nt][p + 2] * inv);
                }
            }
        }
        return;
    }

#pragma unroll
    for (int mt = 0; mt < 4; mt++) {
#pragma unroll
        for (int nt = 0; nt < 8; nt++) {
            const int r0 = m0 + wm * 64 + mt * 16 + gid;
            const int cN = n0 + wn * 64 + nt * 8 + 2 * tig;
#pragma unroll
            for (int half = 0; half < 2; half++) {
                const int r = r0 + half * 8;
                float x = acc[mt][nt][half * 2 + 0];
                float y = acc[mt][nt][half * 2 + 1];
                if (epi == 0) {
                    float2 o = make_float2(x * scale + bias[cN],
                                           y * scale + bias[cN + 1]);
                    *(float2*)&((float*)Dv)[dH * zh + (long long)r * ldd + cN] = o;
                } else if (epi == 4) {
                    __half2 h = __floats2half2_rn(x * scale + bias[cN],
                                                  y * scale + bias[cN + 1]);
                    *(__half2*)&((__half*)Dv)[dH * zh + (long long)r * ldd + cN] = h;
                } else if (epi == 1) {
                    ((__half*)Dv)[(long long)(cN    ) * MVID + r] = __float2half_rn(x);
                    ((__half*)Dv)[(long long)(cN + 1) * MVID + r] = __float2half_rn(y);
                } else {
                    long long addr = (long long)zs * pStride
                                   + (long long)(r >> 5) * 16384
                                   + (long long)zh * 8192
                                   + (r & 31) * 256 + cN;
                    *(float2*)&((float*)Dv)[addr] = make_float2(x, y);
                }
            }
        }
    }
}

// ---------------------------------------------------------------------------
// Merged fp32 -> fp16 converter for all six inputs (8 elems per thread-task)
// ---------------------------------------------------------------------------
#define N8_T  (MTXT * E / 8)          // 131072
#define N8_V  (MVID * E / 8)          // 524288
#define N8_W  (E * E / 8)             // 32768
#define N8_ALL (N8_T + N8_V + 4 * N8_W)

__global__ void cvt_all(const float* __restrict__ t, const float* __restrict__ v,
                        const float* __restrict__ wq, const float* __restrict__ wk,
                        const float* __restrict__ wv, const float* __restrict__ wo,
                        __half* __restrict__ dt, __half* __restrict__ dvh,
                        __half* __restrict__ dwq, __half* __restrict__ dwk,
                        __half* __restrict__ dwv, __half* __restrict__ dwo)
{
    int i = blockIdx.x * blockDim.x + threadIdx.x;
    if (i >= N8_ALL) return;
    const float* s; __half* d; int off;
    if (i < N8_V) { s = v; d = dvh; off = i; }
    else if (i < N8_V + N8_T) { s = t; d = dt; off = i - N8_V; }
    else {
        int j = i - N8_V - N8_T;
        int w = j / N8_W; off = j % N8_W;
        s = (w == 0) ? wq : (w == 1) ? wk : (w == 2) ? wv : wo;
        d = (w == 0) ? dwq : (w == 1) ? dwk : (w == 2) ? dwv : dwo;
    }
    const float4* sp = (const float4*)s + 2 * (long long)off;
    float4 a = sp[0], b = sp[1];
    uint4 o;
    o.x = packh2(a.x, a.y); o.y = packh2(a.z, a.w);
    o.z = packh2(b.x, b.y); o.w = packh2(b.z, b.w);
    *((uint4*)d + off) = o;
}

// Sum the 4 split-K fp32 partials and convert to fp16 (4 elems/thread)
__global__ void sum4cvt(const float* __restrict__ p, __half* __restrict__ d, int n4)
{
    int i = blockIdx.x * blockDim.x + threadIdx.x;
    if (i < n4) {
        const long long st = (long long)MTXT * E / 4;
        float4 v = *((const float4*)p + i);
        float4 b1 = *((const float4*)p + st + i);
        float4 b2 = *((const float4*)p + 2 * st + i);
        float4 b3 = *((const float4*)p + 3 * st + i);
        v.x += b1.x + b2.x + b3.x;
        v.y += b1.y + b2.y + b3.y;
        v.z += b1.z + b2.z + b3.z;
        v.w += b1.w + b2.w + b3.w;
        uint2 o;
        o.x = packh2(v.x, v.y); o.y = packh2(v.z, v.w);
        *((uint2*)d + i) = o;
    }
}

// ---------------------------------------------------------------------------
extern "C" void kernel_launch(void* const* d_in, const int* in_sizes, int n_in,
                              void* d_out, int out_size)
{
    const float* text  = (const float*)d_in[0];
    const float* video = (const float*)d_in[1];
    const float* Wq = (const float*)d_in[2];
    const float* bq = (const float*)d_in[3];
    const float* Wk = (const float*)d_in[4];
    const float* bk = (const float*)d_in[5];
    const float* Wv = (const float*)d_in[6];
    const float* bv = (const float*)d_in[7];
    const float* Wo = (const float*)d_in[8];
    const float* bo = (const float*)d_in[9];
    float* out = (float*)d_out;

    __half *thp, *vhp, *Wqh, *Wkh, *Wvh, *Woh, *Qp, *Kp, *Vtp, *Wtp, *Ahp;
    float* Pp;
    cudaGetSymbolAddress((void**)&thp, g_th);
    cudaGetSymbolAddress((void**)&vhp, g_vh);
    cudaGetSymbolAddress((void**)&Wqh, g_Wqh);
    cudaGetSymbolAddress((void**)&Wkh, g_Wkh);
    cudaGetSymbolAddress((void**)&Wvh, g_Wvh);
    cudaGetSymbolAddress((void**)&Woh, g_Woh);
    cudaGetSymbolAddress((void**)&Qp,  g_Qh);
    cudaGetSymbolAddress((void**)&Kp,  g_Kh);
    cudaGetSymbolAddress((void**)&Vtp, g_Vth);
    cudaGetSymbolAddress((void**)&Wtp, g_Wth);
    cudaGetSymbolAddress((void**)&Pp,  g_part);
    cudaGetSymbolAddress((void**)&Ahp, g_Ah);

    cudaFuncSetAttribute(gemm_h,
                         cudaFuncAttributeMaxDynamicSharedMemorySize, SMEM_BYTES);

    dim3 t(128);

    // ---- merged input conversion to fp16 ----
    cvt_all<<<(N8_ALL + 255) / 256, 256>>>(text, video, Wq, Wk, Wv, Wo,
                                           thp, vhp, Wqh, Wkh, Wvh, Woh);

    // ---- projections ----
    gemm_h<<<dim3(4, 16, 1), t, SMEM_BYTES>>>(thp, 512, 0, 0, Wqh, 512, 0, 0,
        bq, Qp, 512, 1, 0, 4, 512, 0, 1.0f);
    gemm_h<<<dim3(4, 64, 1), t, SMEM_BYTES>>>(vhp, 512, 0, 0, Wkh, 512, 0, 0,
        bk, Kp, 512, 1, 0, 4, 512, 0, 1.0f);
    gemm_h<<<dim3(4, 64, 1), t, SMEM_BYTES>>>(vhp, 512, 0, 0, Wvh, 512, 0, 0,
        bv, Vtp, 512, 1, 0, 1, 0, 0, 1.0f);

    // ---- logits + fused softmax -> Wt[h][bt][av] ----
    gemm_h<<<dim3(16, 64, 2), t, SMEM_BYTES>>>(Kp, 512, 256, 0, Qp, 512, 256, 0,
        nullptr, Wtp, 256, 1, 0, 5, 0, (long long)MTXT * MVID, 1.0f);

    // ---- attention: split-K x4, fp32 partials ----
    gemm_h<<<dim3(2, 16, 2 * NSPLIT), t, SMEM_BYTES>>>(Wtp, MVID,
        (long long)MTXT * MVID, KSPL,
        Vtp, MVID, (long long)HD * MVID, KSPL,
        nullptr, Pp, KSPL, NSPLIT, (long long)MTXT * E, 3, 0, 0, 1.0f);

    // ---- sum partials + convert ----
    sum4cvt<<<1024, 256>>>(Pp, Ahp, MTXT * E / 4);

    // ---- output projection ----
    gemm_h<<<dim3(4, 16, 1), t, SMEM_BYTES>>>(Ahp, 512, 0, 0, Woh, 512, 0, 0,
        bo, out, 512, 1, 0, 0, 512, 0, 1.0f);
}